// round 14
// baseline (speedup 1.0000x reference)
#include <cuda_runtime.h>
#include <cuda_bf16.h>
#include <cstdint>

// FWHT, N = 4096, fp32, Sylvester ordering.  H4096 = H64 (x) H64.
// One CTA (64 threads) per 2 rows, double-buffered via cp.async.bulk:
//   prologue: bulk-load row0 -> buf0, row1 -> buf1 (mbarrier completion)
//   per row : LDS column reads -> fwht64 (bits 11:6) -> rotated smem
//             exchange -> fwht64 (bits 5:0) -> linear STS.128 -> bulk store.
// Load of row1 overlaps all of row0's compute; store of row0 overlaps row1.
// All smem access patterns bank-conflict-free. LSU wf/row: 512 (R9: 768),
// and global traffic rides the bulk-copy engines (no LDG scoreboard pileup).

#define FWHT_N 4096

__device__ __forceinline__ uint32_t smem_u32(const void* p) {
    return (uint32_t)__cvta_generic_to_shared(p);
}

__device__ __forceinline__ void fwht64(float v[64]) {
#pragma unroll
    for (int h = 1; h < 64; h <<= 1) {
#pragma unroll
        for (int i = 0; i < 64; i++) {
            if ((i & h) == 0) {
                float a = v[i];
                float b = v[i + h];
                v[i]     = a + b;
                v[i + h] = a - b;
            }
        }
    }
}

__device__ __forceinline__ void mbar_wait(uint32_t mbar, uint32_t parity) {
    asm volatile(
        "{\n\t"
        ".reg .pred P;\n\t"
        "WAIT_%=:\n\t"
        "mbarrier.try_wait.parity.acquire.cta.shared::cta.b64 P, [%0], %1, 0x989680;\n\t"
        "@!P bra.uni WAIT_%=;\n\t"
        "}"
        :: "r"(mbar), "r"(parity) : "memory");
}

__global__ __launch_bounds__(64, 6)
void HadamardTransform_68891275428167_kernel(const float* __restrict__ x,
                                             float* __restrict__ y) {
    __shared__ __align__(128) float sbuf[2][FWHT_N];        // 2 x 16 KB
    __shared__ __align__(8) unsigned long long mbar[2];

    const int t = threadIdx.x;                               // 0..63
    const size_t row0 = (size_t)blockIdx.x * 2;

    const uint32_t mb0 = smem_u32(&mbar[0]);
    const uint32_t mb1 = smem_u32(&mbar[1]);

    if (t == 0) {
        asm volatile("mbarrier.init.shared.b64 [%0], 1;" :: "r"(mb0) : "memory");
        asm volatile("mbarrier.init.shared.b64 [%0], 1;" :: "r"(mb1) : "memory");
    }
    __syncthreads();

    // ---- Prologue: bulk-load both rows (16 KB each). ----
    if (t == 0) {
        const uint32_t bytes = FWHT_N * 4;
        uint32_t d0 = smem_u32(sbuf[0]);
        uint32_t d1 = smem_u32(sbuf[1]);
        const float* s0 = x + row0 * FWHT_N;
        const float* s1 = s0 + FWHT_N;
        asm volatile("mbarrier.arrive.expect_tx.shared.b64 _, [%0], %1;"
                     :: "r"(mb0), "r"(bytes) : "memory");
        asm volatile("cp.async.bulk.shared::cluster.global.mbarrier::complete_tx::bytes "
                     "[%0], [%1], %2, [%3];"
                     :: "r"(d0), "l"(s0), "r"(bytes), "r"(mb0) : "memory");
        asm volatile("mbarrier.arrive.expect_tx.shared.b64 _, [%0], %1;"
                     :: "r"(mb1), "r"(bytes) : "memory");
        asm volatile("cp.async.bulk.shared::cluster.global.mbarrier::complete_tx::bytes "
                     "[%0], [%1], %2, [%3];"
                     :: "r"(d1), "l"(s1), "r"(bytes), "r"(mb1) : "memory");
    }

    float v[64];

#pragma unroll 1
    for (int rr = 0; rr < 2; rr++) {
        float* s = sbuf[rr];
        mbar_wait(rr == 0 ? mb0 : mb1, 0);

        // ---- Pass-1 read: v[hi] = s[hi*64 + t] (lanes consecutive, CF). ----
#pragma unroll
        for (int hi = 0; hi < 64; hi++)
            v[hi] = s[(hi << 6) + t];
        __syncthreads();          // all reads done before scattered writes

        fwht64(v);                // bits 11:6

        // ---- Exchange write: s[hi*64 + ((t + 4*hi) & 63)], CF. ----
#pragma unroll
        for (int hi = 0; hi < 64; hi++)
            s[(hi << 6) + ((t + (hi << 2)) & 63)] = v[hi];
        __syncthreads();

        // ---- Exchange read: thread t reads its own 256B block as LDS.128,
        //      quads rotated (q + t) & 15; v[4q+j] mapping (R9-proven). ----
        {
            const float4* sv = reinterpret_cast<const float4*>(s + (t << 6));
#pragma unroll
            for (int q = 0; q < 16; q++) {
                float4 f = sv[(q + t) & 15];
                v[4 * q + 0] = f.x;
                v[4 * q + 1] = f.y;
                v[4 * q + 2] = f.z;
                v[4 * q + 3] = f.w;
            }
        }

        fwht64(v);                // bits 5:0

        // ---- Linear STS.128 into own block (rotated order => CF):
        //      s[t*64 + lo] = v[lo]; buffer now holds the final row. ----
        {
            float4* sv = reinterpret_cast<float4*>(s + (t << 6));
#pragma unroll
            for (int q = 0; q < 16; q++) {
                const int qq = (q + t) & 15;
                sv[qq] = make_float4(v[4 * qq + 0], v[4 * qq + 1],
                                     v[4 * qq + 2], v[4 * qq + 3]);
            }
        }
        __syncthreads();

        // ---- Bulk store row (async; overlaps next row's compute). ----
        if (t == 0) {
            asm volatile("fence.proxy.async.shared::cta;" ::: "memory");
            float* gdst = y + (row0 + rr) * FWHT_N;
            uint32_t ssrc = smem_u32(s);
            asm volatile("cp.async.bulk.global.shared::cta.bulk_group "
                         "[%0], [%1], %2;"
                         :: "l"(gdst), "r"(ssrc), "r"((uint32_t)(FWHT_N * 4))
                         : "memory");
            asm volatile("cp.async.bulk.commit_group;" ::: "memory");
        }
    }

    // Drain outstanding bulk stores before CTA retirement frees smem.
    if (t == 0)
        asm volatile("cp.async.bulk.wait_group 0;" ::: "memory");
}

extern "C" void kernel_launch(void* const* d_in, const int* in_sizes, int n_in,
                              void* d_out, int out_size) {
    const float* x = (const float*)d_in[0];
    float* y = (float*)d_out;

    const int rows = in_sizes[0] / FWHT_N;   // 16384
    HadamardTransform_68891275428167_kernel<<<rows / 2, 64>>>(x, y);
}